// round 12
// baseline (speedup 1.0000x reference)
#include <cuda_runtime.h>
#include <cuda_fp16.h>

#define N_NODES 100000
#define DIM     64
#define NB      8192
#define KP      32
#define KN      100
#define INV255  (1.0f / 255.0f)
#define B_PER_BLK 8

// Scratch (__device__ globals; left zeroed after every execution -> deterministic).
__device__ unsigned g_Zq[N_NODES * 16];   // 6.4 MB, u8-quantized sigmoid(P), 64B/row
__device__ float    g_acc[3];             // [0]=sumsq deg, [1]=adj, [2]=deg_dist
__device__ unsigned g_count;              // finalize election counter

// ---------------------------------------------------------------------------
// Prep: sigmoid(P) -> u8 g_Zq (x255), plus degree-loss sum of squares.
// float4 per lane: one warp covers 2 rows (lanes 0-15 row A, 16-31 row B).
__global__ void prep_kernel(const float* __restrict__ P,
                            const float* __restrict__ W,
                            const float* __restrict__ deg) {
    const int lane   = threadIdx.x & 31;
    const int warp   = (blockIdx.x * blockDim.x + threadIdx.x) >> 5;
    const int nwarps = (gridDim.x * blockDim.x) >> 5;
    const int sub    = lane >> 4;          // 0 or 1: which row of the pair
    const int q      = lane & 15;          // owns floats [q*4, q*4+4)

    const float4 w = *(const float4*)(W + q * 4);

    float acc = 0.0f;
    for (int pair = warp; pair < N_NODES / 2; pair += nwarps) {
        const int row = pair * 2 + sub;
        const float4 p = *(const float4*)(P + (size_t)row * DIM + q * 4);
        const float z0 = 1.0f / (1.0f + __expf(-p.x));
        const float z1 = 1.0f / (1.0f + __expf(-p.y));
        const float z2 = 1.0f / (1.0f + __expf(-p.z));
        const float z3 = 1.0f / (1.0f + __expf(-p.w));

        const unsigned packed =
              __float2uint_rn(z0 * 255.0f)
            | (__float2uint_rn(z1 * 255.0f) << 8)
            | (__float2uint_rn(z2 * 255.0f) << 16)
            | (__float2uint_rn(z3 * 255.0f) << 24);
        g_Zq[row * 16 + q] = packed;       // warp writes 128B contiguous

        float s = z0 * w.x + z1 * w.y + z2 * w.z + z3 * w.w;
        #pragma unroll
        for (int o = 8; o; o >>= 1) s += __shfl_xor_sync(0xFFFFFFFFu, s, o);
        if (q == 0) {                       // lanes 0 and 16 hold row sums
            const float dd = s - deg[row];
            acc += dd * dd;
        }
    }

    #pragma unroll
    for (int o = 16; o; o >>= 1) acc += __shfl_xor_sync(0xFFFFFFFFu, acc, o);

    __shared__ float sh[32];
    if (lane == 0) sh[threadIdx.x >> 5] = acc;
    __syncthreads();
    if (threadIdx.x == 0) {
        float t = 0.0f;
        const int nw = blockDim.x >> 5;
        for (int i = 0; i < nw; i++) t += sh[i];
        atomicAdd(&g_acc[0], t);
    }
}

// ---------------------------------------------------------------------------
// One warp per selected node b; 8 b's per block. NEW layout: 16 lanes own one
// gathered 64B row (4B/lane) -> each LDG touches only 2 cache lines, cutting
// within-LDG replay wavefront generation (2.07 cyc/wf) vs the 8-line layout.
// Warp processes 2 neighbor rows per iteration (halves h=0/1).
__global__ __launch_bounds__(256) void contrast_kernel(
        const int* __restrict__ sel,
        const int* __restrict__ pos_adj,
        const int* __restrict__ neg_adj,
        const int* __restrict__ pos_deg,
        const int* __restrict__ neg_deg,
        float* __restrict__ out) {
    __shared__ unsigned s_pos[2][B_PER_BLK][KP];   // pre-scaled offsets (idx*16)
    __shared__ unsigned s_neg[2][B_PER_BLK][KN];
    __shared__ int      s_sel[B_PER_BLK];

    const int tid  = threadIdx.x;
    const int warp = tid >> 5;
    const int lane = tid & 31;
    const int b_base = blockIdx.x * B_PER_BLK;

    // ---- stage all indices for this block (fully coalesced) ----
    ((unsigned*)s_pos[0])[tid] = (unsigned)pos_adj[b_base * KP + tid] * 16u;
    ((unsigned*)s_pos[1])[tid] = (unsigned)pos_deg[b_base * KP + tid] * 16u;
    #pragma unroll
    for (int i = 0; i < 4; i++) {                            // 800 <= 4*256
        const int j = tid + i * 256;
        if (j < B_PER_BLK * KN) {
            ((unsigned*)s_neg[0])[j] = (unsigned)neg_adj[b_base * KN + j] * 16u;
            ((unsigned*)s_neg[1])[j] = (unsigned)neg_deg[b_base * KN + j] * 16u;
        }
    }
    if (tid < B_PER_BLK) s_sel[tid] = sel[b_base + tid];
    __syncthreads();

    const int h = lane >> 4;              // half: which row of the pair
    const int c = lane & 15;              // owns uint c (4B) of the 64B row

    // Zi column for this lane (same in both halves).
    const unsigned zi = g_Zq[s_sel[warp] * 16 + c];

    float val[2];
    #pragma unroll
    for (int which = 0; which < 2; which++) {
        // Positives: per-lane int accumulation over this half's 16 rows.
        unsigned pos_acc = 0u;
        #pragma unroll
        for (int kb = 0; kb < KP; kb += 2) {
            const unsigned off = s_pos[which][warp][kb + h];
            const unsigned r = g_Zq[off + c];
            pos_acc = __dp4a(__vabsdiffu4(zi, r), 0x01010101u, pos_acc);
        }
        // full-warp reduce (covers both halves + 16 columns)
        #pragma unroll
        for (int o = 16; o; o >>= 1)
            pos_acc += __shfl_xor_sync(0xFFFFFFFFu, pos_acc, o);

        // Negatives: 50 exact pair-iterations (100 rows).
        float negsum = 0.0f;
        #pragma unroll 10
        for (int kb = 0; kb < KN; kb += 2) {
            const unsigned off = s_neg[which][warp][kb + h];
            const unsigned r = g_Zq[off + c];
            unsigned s = __dp4a(__vabsdiffu4(zi, r), 0x01010101u, 0u);
            // reduce within each 16-lane half (xor<16 stays in-half)
            s += __shfl_xor_sync(0xFFFFFFFFu, s, 1);
            s += __shfl_xor_sync(0xFFFFFFFFu, s, 2);
            s += __shfl_xor_sync(0xFFFFFFFFu, s, 4);
            s += __shfl_xor_sync(0xFFFFFFFFu, s, 8);
            negsum += __expf(__uint2float_rn(s) * INV255);
        }
        // combine the two halves' partial exp-sums
        negsum += __shfl_xor_sync(0xFFFFFFFFu, negsum, 16);

        val[which] = -__uint2float_rn(pos_acc) * (INV255 / KP) + __logf(negsum);
    }

    __shared__ float sh1[8], sh2[8];
    __shared__ bool  sh_last;
    if (lane == 0) {
        sh1[warp] = val[0];
        sh2[warp] = val[1];
    }
    __syncthreads();
    if (tid == 0) {
        float t1 = 0.0f, t2 = 0.0f;
        #pragma unroll
        for (int i = 0; i < 8; i++) { t1 += sh1[i]; t2 += sh2[i]; }
        atomicAdd(&g_acc[1], t1);
        atomicAdd(&g_acc[2], t2);
        __threadfence();
        sh_last = (atomicAdd(&g_count, 1u) == gridDim.x - 1);
    }
    __syncthreads();
    if (tid == 0 && sh_last) {
        const float a0 = *(volatile float*)&g_acc[0];
        const float a1 = *(volatile float*)&g_acc[1];
        const float a2 = *(volatile float*)&g_acc[2];
        out[0] = sqrtf(a0);
        out[1] = a1 * (1.0f / N_NODES);
        out[2] = a2 * (1.0f / N_NODES);
        g_acc[0] = 0.0f; g_acc[1] = 0.0f; g_acc[2] = 0.0f;
        g_count = 0u;
    }
}

// ---------------------------------------------------------------------------
extern "C" void kernel_launch(void* const* d_in, const int* in_sizes, int n_in,
                              void* d_out, int out_size) {
    const float* P   = (const float*)d_in[0];
    const float* W   = (const float*)d_in[1];
    const float* deg = (const float*)d_in[2];
    const int* sel   = (const int*)d_in[3];
    const int* pa    = (const int*)d_in[4];
    const int* na    = (const int*)d_in[5];
    const int* pd    = (const int*)d_in[6];
    const int* nd    = (const int*)d_in[7];
    float* out = (float*)d_out;

    prep_kernel<<<256, 1024>>>(P, W, deg);
    contrast_kernel<<<NB / B_PER_BLK, 256>>>(sel, pa, na, pd, nd, out);
}

// round 13
// speedup vs baseline: 1.5382x; 1.5382x over previous
#include <cuda_runtime.h>
#include <cuda_fp16.h>

#define N_NODES 100000
#define DIM     64
#define NB      8192
#define KP      32
#define KN      100
#define INV255  (1.0f / 255.0f)

// Scratch (__device__ globals; left zeroed after every execution -> deterministic).
__device__ unsigned g_Zq[N_NODES * 16];   // 6.4 MB, u8-quantized sigmoid(P), 64B/row
__device__ float    g_acc[3];             // [0]=sumsq deg, [1]=adj, [2]=deg_dist
__device__ unsigned g_count;              // finalize election counter

// ---------------------------------------------------------------------------
// Prep: sigmoid(P) -> u8 g_Zq (x255), plus degree-loss sum of squares.
// float4 per lane: one warp covers 2 rows (lanes 0-15 row A, 16-31 row B).
__global__ void prep_kernel(const float* __restrict__ P,
                            const float* __restrict__ W,
                            const float* __restrict__ deg) {
    const int lane   = threadIdx.x & 31;
    const int warp   = (blockIdx.x * blockDim.x + threadIdx.x) >> 5;
    const int nwarps = (gridDim.x * blockDim.x) >> 5;
    const int sub    = lane >> 4;          // 0 or 1: which row of the pair
    const int q      = lane & 15;          // owns floats [q*4, q*4+4)

    const float4 w = *(const float4*)(W + q * 4);

    float acc = 0.0f;
    for (int pair = warp; pair < N_NODES / 2; pair += nwarps) {
        const int row = pair * 2 + sub;
        const float4 p = *(const float4*)(P + (size_t)row * DIM + q * 4);
        const float z0 = 1.0f / (1.0f + __expf(-p.x));
        const float z1 = 1.0f / (1.0f + __expf(-p.y));
        const float z2 = 1.0f / (1.0f + __expf(-p.z));
        const float z3 = 1.0f / (1.0f + __expf(-p.w));

        const unsigned packed =
              __float2uint_rn(z0 * 255.0f)
            | (__float2uint_rn(z1 * 255.0f) << 8)
            | (__float2uint_rn(z2 * 255.0f) << 16)
            | (__float2uint_rn(z3 * 255.0f) << 24);
        g_Zq[row * 16 + q] = packed;       // warp writes 128B contiguous

        float s = z0 * w.x + z1 * w.y + z2 * w.z + z3 * w.w;
        #pragma unroll
        for (int o = 8; o; o >>= 1) s += __shfl_xor_sync(0xFFFFFFFFu, s, o);
        if (q == 0) {                       // lanes 0 and 16 hold row sums
            const float dd = s - deg[row];
            acc += dd * dd;
        }
    }

    #pragma unroll
    for (int o = 16; o; o >>= 1) acc += __shfl_xor_sync(0xFFFFFFFFu, acc, o);

    __shared__ float sh[32];
    if (lane == 0) sh[threadIdx.x >> 5] = acc;
    __syncthreads();
    if (threadIdx.x == 0) {
        float t = 0.0f;
        const int nw = blockDim.x >> 5;
        for (int i = 0; i < nw; i++) t += sh[i];
        atomicAdd(&g_acc[0], t);
    }
}

// ---------------------------------------------------------------------------
// SAD over this lane's 16 dims (16B of a 64B row): 4x VABSDIFF4 + 4x IDP4A.
__device__ __forceinline__ unsigned sad16(uint4 r, uint4 zi, unsigned acc) {
    acc = __dp4a(__vabsdiffu4(zi.x, r.x), 0x01010101u, acc);
    acc = __dp4a(__vabsdiffu4(zi.y, r.y), 0x01010101u, acc);
    acc = __dp4a(__vabsdiffu4(zi.z, r.z), 0x01010101u, acc);
    acc = __dp4a(__vabsdiffu4(zi.w, r.w), 0x01010101u, acc);
    return acc;
}

// One warp per selected node b. 4-lane groups each own one gathered 64B row;
// a warp processes 8 neighbor rows per iteration. Last block finalizes.
// (Empirically fastest form: direct index LDGs, default occupancy, 32 regs.)
__global__ __launch_bounds__(256) void contrast_kernel(
        const int* __restrict__ sel,
        const int* __restrict__ pos_adj,
        const int* __restrict__ neg_adj,
        const int* __restrict__ pos_deg,
        const int* __restrict__ neg_deg,
        float* __restrict__ out) {
    const int warp = (blockIdx.x * blockDim.x + threadIdx.x) >> 5;
    const int lane = threadIdx.x & 31;
    const int b  = warp;                  // grid sized exactly: 1024*8 = NB warps
    const int g  = lane >> 2;             // neighbor-group 0..7
    const int gl = lane & 3;              // owns dims [gl*16, gl*16+16)

    const uint4 zi = *(const uint4*)(g_Zq + sel[b] * 16 + gl * 4);

    float val[2];
    #pragma unroll
    for (int which = 0; which < 2; which++) {
        const int* plist = which ? pos_deg : pos_adj;
        const int* nlist = which ? neg_deg : neg_adj;

        // Positives: pure int accumulation, one butterfly at the end.
        unsigned pos_acc = 0u;
        #pragma unroll
        for (int kb = 0; kb < KP; kb += 8) {
            const int idx = plist[b * KP + kb + g];
            pos_acc = sad16(*(const uint4*)(g_Zq + idx * 16 + gl * 4), zi, pos_acc);
        }
        #pragma unroll
        for (int o = 16; o; o >>= 1)
            pos_acc += __shfl_xor_sync(0xFFFFFFFFu, pos_acc, o);

        // Negatives: 12 full iterations of 8 rows + tail of 4 rows.
        float negsum = 0.0f;
        #pragma unroll 4
        for (int kb = 0; kb < 96; kb += 8) {
            const int idx = nlist[b * KN + kb + g];
            unsigned s = sad16(*(const uint4*)(g_Zq + idx * 16 + gl * 4), zi, 0u);
            s += __shfl_xor_sync(0xFFFFFFFFu, s, 1);
            s += __shfl_xor_sync(0xFFFFFFFFu, s, 2);
            negsum += __expf(__uint2float_rn(s) * INV255);
        }
        {   // tail: rows 96..99 handled by groups 0..3
            const int idx = nlist[b * KN + 96 + (g & 3)];
            unsigned s = sad16(*(const uint4*)(g_Zq + idx * 16 + gl * 4), zi, 0u);
            s += __shfl_xor_sync(0xFFFFFFFFu, s, 1);
            s += __shfl_xor_sync(0xFFFFFFFFu, s, 2);
            if (g < 4) negsum += __expf(__uint2float_rn(s) * INV255);
        }
        negsum += __shfl_xor_sync(0xFFFFFFFFu, negsum, 4);
        negsum += __shfl_xor_sync(0xFFFFFFFFu, negsum, 8);
        negsum += __shfl_xor_sync(0xFFFFFFFFu, negsum, 16);

        val[which] = -__uint2float_rn(pos_acc) * (INV255 / KP) + __logf(negsum);
    }

    __shared__ float sh1[8], sh2[8];
    __shared__ bool  sh_last;
    const int wib = (threadIdx.x >> 5);
    if (lane == 0) {
        sh1[wib] = val[0];
        sh2[wib] = val[1];
    }
    __syncthreads();
    if (threadIdx.x == 0) {
        float t1 = 0.0f, t2 = 0.0f;
        #pragma unroll
        for (int i = 0; i < 8; i++) { t1 += sh1[i]; t2 += sh2[i]; }
        atomicAdd(&g_acc[1], t1);
        atomicAdd(&g_acc[2], t2);
        __threadfence();
        sh_last = (atomicAdd(&g_count, 1u) == gridDim.x - 1);
    }
    __syncthreads();
    if (threadIdx.x == 0 && sh_last) {
        const float a0 = *(volatile float*)&g_acc[0];
        const float a1 = *(volatile float*)&g_acc[1];
        const float a2 = *(volatile float*)&g_acc[2];
        out[0] = sqrtf(a0);
        out[1] = a1 * (1.0f / N_NODES);
        out[2] = a2 * (1.0f / N_NODES);
        g_acc[0] = 0.0f; g_acc[1] = 0.0f; g_acc[2] = 0.0f;
        g_count = 0u;
    }
}

// ---------------------------------------------------------------------------
extern "C" void kernel_launch(void* const* d_in, const int* in_sizes, int n_in,
                              void* d_out, int out_size) {
    const float* P   = (const float*)d_in[0];
    const float* W   = (const float*)d_in[1];
    const float* deg = (const float*)d_in[2];
    const int* sel   = (const int*)d_in[3];
    const int* pa    = (const int*)d_in[4];
    const int* na    = (const int*)d_in[5];
    const int* pd    = (const int*)d_in[6];
    const int* nd    = (const int*)d_in[7];
    float* out = (float*)d_out;

    prep_kernel<<<256, 1024>>>(P, W, deg);
    contrast_kernel<<<NB / 8, 256>>>(sel, pa, na, pd, nd, out);
}